// round 16
// baseline (speedup 1.0000x reference)
#include <cuda_runtime.h>
#include <cuda_bf16.h>
#include <cstdint>

#define BB 256
#define LL 1024
#define DD 126
#define TT 128
#define NTH 256
#define NSEQ 8
#define NCTA 32
#define NEGV -10000.0f
#define LN2 0.6931471805599453

__device__ int g_perm[BB];

// Rank batches by length (descending, index tie-break). O(n^2) rank, n=256.
__global__ void rank_kernel(const int* __restrict__ x_len) {
    __shared__ int lens[BB];
    int t = threadIdx.x;
    lens[t] = x_len[t];
    __syncthreads();
    int mylen = lens[t];
    int r = 0;
    for (int j = 0; j < BB; ++j) {
        int lj = lens[j];
        if (lj > mylen || (lj == mylen && j < t)) r++;
    }
    g_perm[r] = t;
}

__device__ __forceinline__ uint32_t smem_u32(const void* p) {
    uint32_t a;
    asm("{ .reg .u64 t; cvta.to.shared.u64 t, %1; cvt.u32.u64 %0, t; }" : "=r"(a) : "l"(p));
    return a;
}
__device__ __forceinline__ uint32_t packbf2(float lo, float hi) {
    __nv_bfloat162 v = __floats2bfloat162_rn(lo, hi);
    return *reinterpret_cast<uint32_t*>(&v);
}
__device__ __forceinline__ uint16_t bf16b(float f) {
    __nv_bfloat16 v = __float2bfloat16(f);
    return *reinterpret_cast<uint16_t*>(&v);
}
__device__ __forceinline__ void ldsm4t(uint32_t& r0, uint32_t& r1, uint32_t& r2, uint32_t& r3,
                                       uint32_t addr) {
    asm volatile("ldmatrix.sync.aligned.m8n8.x4.trans.shared.b16 {%0,%1,%2,%3}, [%4];"
                 : "=r"(r0), "=r"(r1), "=r"(r2), "=r"(r3) : "r"(addr));
}
__device__ __forceinline__ void mma16816(float& c0, float& c1, float& c2, float& c3,
                                         uint32_t a0, uint32_t a1, uint32_t a2, uint32_t a3,
                                         uint32_t b0, uint32_t b1) {
    asm volatile(
        "mma.sync.aligned.m16n8k16.row.col.f32.bf16.bf16.f32 "
        "{%0,%1,%2,%3}, {%4,%5,%6,%7}, {%8,%9}, {%0,%1,%2,%3};"
        : "+f"(c0), "+f"(c1), "+f"(c2), "+f"(c3)
        : "r"(a0), "r"(a1), "r"(a2), "r"(a3), "r"(b0), "r"(b1));
}

__global__ __launch_bounds__(NTH, 1) void crf_kernel(
    const float* __restrict__ x,
    const float* __restrict__ trans,
    const int*   __restrict__ x_len,
    const int*   __restrict__ tags,
    float*       __restrict__ out)
{
    // B tile: [2 buffers][128 k-rows][8 seq] bf16, row = 16 B
    __shared__ __align__(16) uint8_t sB[2][2048];
    // E buffer: [2][128 rows][8 seq] bf16, row pitch 20 B (bank-spread)
    __shared__ __align__(16) uint8_t sE[2][2560];
    __shared__ uint32_t s_rp[2][4];   // [buf][t]: bf16x2 (r_{2t}, r_{2t+1})
    __shared__ int s_len[NSEQ], s_b[NSEQ], s_ci[NSEQ];
    __shared__ float s_em[NSEQ], s_tr[NSEQ];
    __shared__ float s_S[4][NSEQ];

    int tid  = threadIdx.x;
    int warp = tid >> 5;
    int lane = tid & 31;
    int g = lane >> 2;      // fragment groupID (row offset)
    int t = lane & 3;       // fragment threadID_in_group (col pair / k pair)
    int c = blockIdx.x;

    if (tid < NSEQ) {
        int b = g_perm[c * NSEQ + tid];
        s_b[tid] = b;
        s_len[tid] = x_len[b];
    }
    if (tid < 8) s_rp[tid >> 2][tid & 3] = 0x3F803F80u;   // r = 1.0 pairs
    for (int q = tid; q < 1024; q += NTH) ((uint32_t*)sB)[q] = 0;
    for (int q = tid; q < 1280; q += NTH) ((uint32_t*)sE)[q] = 0;
    __syncthreads();

    // w0 one-hot at START=126 (buffer 0)
    if (tid < NSEQ) *(uint16_t*)(sB[0] + 126 * 16 + tid * 2) = 0x3F80;

    // A fragments: exp(T), rows 16*warp..+15, static for all steps
    uint32_t A[8][4];
    {
        int r0 = 16 * warp + g, r8 = r0 + 8;
#pragma unroll
        for (int k = 0; k < 8; ++k) {
            int c0 = 16 * k + 2 * t;
            A[k][0] = packbf2(__expf(trans[r0 * TT + c0]), __expf(trans[r0 * TT + c0 + 1]));
            A[k][1] = packbf2(__expf(trans[r8 * TT + c0]), __expf(trans[r8 * TT + c0 + 1]));
            A[k][2] = packbf2(__expf(trans[r0 * TT + c0 + 8]), __expf(trans[r0 * TT + c0 + 9]));
            A[k][3] = packbf2(__expf(trans[r8 * TT + c0 + 8]), __expf(trans[r8 * TT + c0 + 9]));
        }
    }

    int myb  = s_b[warp];
    int mylen = s_len[warp];
    int Lg   = s_len[0];                       // group max (sorted desc)
    int len0 = s_len[2 * t], len1 = s_len[2 * t + 1];
    const float* xw = x + (size_t)myb * LL * DD;

    // emission + transition score for seq = warp
    {
        const int* tg_ = tags + myb * LL;
        float em = 0.f, tr = 0.f;
        for (int l2 = lane; l2 < mylen; l2 += 32) {
            int tgv = tg_[l2];
            em += xw[(size_t)l2 * DD + tgv];
            int prev = l2 ? tg_[l2 - 1] : DD;
            tr += trans[tgv * TT + prev];
            if (l2 == mylen - 1) tr += trans[127 * TT + tgv];
        }
#pragma unroll
        for (int o = 16; o; o >>= 1) {
            em += __shfl_xor_sync(0xffffffffu, em, o);
            tr += __shfl_xor_sync(0xffffffffu, tr, o);
        }
        if (lane == 0) { s_em[warp] = em; s_tr[warp] = tr; }
    }

    // Prime E(l=0) and raw ring (x at l=1,2,3 clamped)
    float raw0[4], raw1[4], raw2[4];
    {
#pragma unroll
        for (int j = 0; j < 4; ++j) {
            int r = lane + 32 * j;
            if (j < 3 || lane < DD - 96)
                *(uint16_t*)(sE[0] + r * 20 + warp * 2) = bf16b(__expf(xw[r]));
        }
        int i1 = (1 < Lg) ? 1 : Lg - 1;
        int i2 = (2 < Lg) ? 2 : Lg - 1;
        int i3 = (3 < Lg) ? 3 : Lg - 1;
#pragma unroll
        for (int j = 0; j < 4; ++j) {
            int r = lane + 32 * j;
            raw0[j] = (r < DD) ? xw[(size_t)i1 * DD + r] : NEGV;
            raw1[j] = (r < DD) ? xw[(size_t)i2 * DD + r] : NEGV;
            raw2[j] = (r < DD) ? xw[(size_t)i3 * DD + r] : NEGV;
        }
    }

    int Ci0 = 0, Ci1 = 0, pend0 = 0, pend1 = 0;
    uint32_t sbB = smem_u32(sB);
    __syncthreads();

    for (int l = 0; l < Lg; ++l) {
        int buf = l & 1;
        // B fragments: 4x ldmatrix.x4.trans, lane -> k-row = lane (+32 per instr)
        uint32_t b[16];
        uint32_t baddr = sbB + buf * 2048 + lane * 16;
        ldsm4t(b[0],  b[1],  b[2],  b[3],  baddr);
        ldsm4t(b[4],  b[5],  b[6],  b[7],  baddr + 512);
        ldsm4t(b[8],  b[9],  b[10], b[11], baddr + 1024);
        ldsm4t(b[12], b[13], b[14], b[15], baddr + 1536);

        float cc0 = 0.f, cc1 = 0.f, cc2 = 0.f, cc3 = 0.f;
        float cd0 = 0.f, cd1 = 0.f, cd2 = 0.f, cd3 = 0.f;
        mma16816(cc0, cc1, cc2, cc3, A[0][0], A[0][1], A[0][2], A[0][3], b[0],  b[1]);
        mma16816(cc0, cc1, cc2, cc3, A[1][0], A[1][1], A[1][2], A[1][3], b[2],  b[3]);
        mma16816(cc0, cc1, cc2, cc3, A[2][0], A[2][1], A[2][2], A[2][3], b[4],  b[5]);
        mma16816(cc0, cc1, cc2, cc3, A[3][0], A[3][1], A[3][2], A[3][3], b[6],  b[7]);
        mma16816(cd0, cd1, cd2, cd3, A[4][0], A[4][1], A[4][2], A[4][3], b[8],  b[9]);
        mma16816(cd0, cd1, cd2, cd3, A[5][0], A[5][1], A[5][2], A[5][3], b[10], b[11]);
        mma16816(cd0, cd1, cd2, cd3, A[6][0], A[6][1], A[6][2], A[6][3], b[12], b[13]);
        mma16816(cd0, cd1, cd2, cd3, A[7][0], A[7][1], A[7][2], A[7][3], b[14], b[15]);
        float c0 = cc0 + cd0, c1 = cc1 + cd1, c2 = cc2 + cd2, c3 = cc3 + cd3;

        // scale factors (independent of MMA -> loads overlap)
        uint32_t rp = s_rp[buf][t];
        int rbase = 16 * warp + g;
        uint32_t e2a = *(const uint32_t*)(sE[buf] + rbase * 20 + t * 4);
        uint32_t e2b = *(const uint32_t*)(sE[buf] + (rbase + 8) * 20 + t * 4);
        float r0f = __uint_as_float(rp << 16);
        float r1f = __uint_as_float(rp & 0xFFFF0000u);
        float w0 = c0 * __uint_as_float(e2a << 16) * r0f;
        float w1 = c1 * __uint_as_float(e2a & 0xFFFF0000u) * r1f;
        float w2 = c2 * __uint_as_float(e2b << 16) * r0f;
        float w3 = c3 * __uint_as_float(e2b & 0xFFFF0000u) * r1f;

        // emission staging: E_{l+1} from ring, reload ring with x[l+4]
        {
            uint8_t* eb = sE[buf ^ 1];
#pragma unroll
            for (int j = 0; j < 4; ++j) {
                int r = lane + 32 * j;
                if (j < 3 || lane < DD - 96)
                    *(uint16_t*)(eb + r * 20 + warp * 2) = bf16b(__expf(raw0[j]));
            }
            int idx = l + 4; if (idx > Lg - 1) idx = Lg - 1;
            const float* src = xw + (size_t)idx * DD;
#pragma unroll
            for (int j = 0; j < 4; ++j) {
                raw0[j] = raw1[j];
                raw1[j] = raw2[j];
                int r = lane + 32 * j;
                raw2[j] = (r < DD) ? src[r] : NEGV;
            }
        }

        // store new w (predicated per-seq: frozen seqs keep their value)
        {
            uint8_t* bB = sB[buf ^ 1];
            int rbytes = rbase * 16 + t * 4;
            if (l < len0) *(uint16_t*)(bB + rbytes)           = bf16b(w0);
            if (l < len1) *(uint16_t*)(bB + rbytes + 2)       = bf16b(w1);
            if (l < len0) *(uint16_t*)(bB + rbytes + 128)     = bf16b(w2);
            if (l < len1) *(uint16_t*)(bB + rbytes + 128 + 2) = bf16b(w3);
        }

        // publisher: warp 7 (first-arbitrated), lanes 0..3 own row 112 = all 8 seqs
        if (warp == 7 && g == 0) {
            uint32_t u0 = __float_as_uint(w0);
            uint32_t u1 = __float_as_uint(w1);
            if (l < len0) { Ci0 += pend0; pend0 = (int)(u0 >> 23) - 127; }
            if (l < len1) { Ci1 += pend1; pend1 = (int)(u1 >> 23) - 127; }
            uint32_t nr0 = (0x7F000000u - (u0 & 0x7F800000u)) >> 16;
            uint32_t nr1 = (0x7F000000u - (u1 & 0x7F800000u)) & 0xFFFF0000u;
            s_rp[buf ^ 1][t] = nr0 | nr1;
        }
        __syncthreads();
    }

    if (warp == 7 && lane < 4) {
        s_ci[2 * lane] = Ci0;
        s_ci[2 * lane + 1] = Ci1;
    }
    __syncthreads();

    // ---- partition: w_final for seq s is in buffer (len_s & 1) ----
    if (tid < TT) {
        float eTs = __expf(trans[127 * TT + tid]);
        const uint16_t* r0p = (const uint16_t*)(sB[0] + tid * 16);
        const uint16_t* r1p = (const uint16_t*)(sB[1] + tid * 16);
        float v[NSEQ];
#pragma unroll
        for (int s = 0; s < NSEQ; ++s) {
            uint16_t h = (s_len[s] & 1) ? r1p[s] : r0p[s];
            v[s] = __uint_as_float((uint32_t)h << 16) * eTs;
        }
#pragma unroll
        for (int o = 16; o; o >>= 1)
#pragma unroll
            for (int s = 0; s < NSEQ; ++s)
                v[s] += __shfl_xor_sync(0xffffffffu, v[s], o);
        if (lane == 0)
#pragma unroll
            for (int s = 0; s < NSEQ; ++s) s_S[warp][s] = v[s];
    }
    __syncthreads();
    if (tid < NSEQ) {
        int s = tid;
        float S = s_S[0][s] + s_S[1][s] + s_S[2][s] + s_S[3][s];
        float part = (float)((double)s_ci[s] * LN2) + logf(S);
        out[s_b[s]] = s_tr[s] + s_em[s] - part;
    }
}

extern "C" void kernel_launch(void* const* d_in, const int* in_sizes, int n_in,
                              void* d_out, int out_size) {
    const float* x     = (const float*)d_in[0];
    const float* trans = (const float*)d_in[1];
    // d_in[2] = x_mask (unused; prefix mask derived from x_len)
    const int*   xlen  = (const int*)d_in[3];
    const int*   tags  = (const int*)d_in[4];
    float* out = (float*)d_out;

    rank_kernel<<<1, BB>>>(xlen);
    crf_kernel<<<NCTA, NTH>>>(x, trans, xlen, tags, out);
}